// round 1
// baseline (speedup 1.0000x reference)
#include <cuda_runtime.h>
#include <math.h>

#define NN 100000
#define EE 1600000

// ---- scratch (device globals; no allocation allowed) ----
__device__ float g_z[(size_t)NN * 512];    // z[n][k*64+o]  (204.8 MB)
__device__ float g_aux[(size_t)NN * 128];  // [n][0:64]=root term, [n][64:128]=skip pre-BN
__device__ float g_agg[(size_t)NN * 64];   // edge aggregation target (25.6 MB, L2-resident)
__device__ float g_h[(size_t)NN * 64];     // h (layer1 act) then h2 pre-BN
__device__ float g_cnt[NN];
__device__ float g_sum[192];               // BN col sums: slot0=h1, slot1=skip, slot2=h2
__device__ float g_sq[192];
__device__ float g_scale[192];
__device__ float g_shift[192];

// ---------------- z1: out = x @ [W1(8x32x64) | root1 | W_skip] ----------------
__global__ void __launch_bounds__(256) z1_kernel(const float* __restrict__ x,
                                                 const float* __restrict__ W1,
                                                 const float* __restrict__ root1,
                                                 const float* __restrict__ Wskip) {
    __shared__ float xs[64][33];
    __shared__ float Wc[32][64];
    int tid = threadIdx.x;
    int n0 = blockIdx.x * 64;
    int chunk = blockIdx.y;  // 0..7: W1 slice k; 8: root1; 9: W_skip

    for (int j = tid; j < 64 * 32; j += 256) {
        int nl = j >> 5, i = j & 31;
        int n = n0 + nl;
        xs[nl][i] = (n < NN) ? x[n * 32 + i] : 0.f;
    }
    for (int j = tid; j < 32 * 64; j += 256) {
        int i = j >> 6, o = j & 63;
        float w;
        if (chunk < 8)       w = W1[chunk * 2048 + i * 64 + o];
        else if (chunk == 8) w = root1[i * 64 + o];
        else                 w = Wskip[i * 64 + o];
        Wc[i][o] = w;
    }
    __syncthreads();

    int oc = tid & 31;   // columns oc, oc+32
    int g  = tid >> 5;   // node group: nodes g*8 .. g*8+7
    float a0[8], a1[8];
#pragma unroll
    for (int r = 0; r < 8; r++) { a0[r] = 0.f; a1[r] = 0.f; }
#pragma unroll
    for (int i = 0; i < 32; i++) {
        float w0 = Wc[i][oc], w1 = Wc[i][oc + 32];
#pragma unroll
        for (int r = 0; r < 8; r++) {
            float xv = xs[g * 8 + r][i];
            a0[r] += xv * w0;
            a1[r] += xv * w1;
        }
    }
#pragma unroll
    for (int r = 0; r < 8; r++) {
        int n = n0 + g * 8 + r;
        if (n >= NN) break;
        if (chunk < 8) {
            g_z[(size_t)n * 512 + chunk * 64 + oc]      = a0[r];
            g_z[(size_t)n * 512 + chunk * 64 + oc + 32] = a1[r];
        } else if (chunk == 8) {
            g_aux[n * 128 + oc]      = a0[r];
            g_aux[n * 128 + oc + 32] = a1[r];
        } else {
            g_aux[n * 128 + 64 + oc]      = a0[r];
            g_aux[n * 128 + 64 + oc + 32] = a1[r];
        }
    }
}

// ---------------- z2: out = h @ [W2(8x64x64) | root2] ----------------
__global__ void __launch_bounds__(256) z2_kernel(const float* __restrict__ W2,
                                                 const float* __restrict__ root2) {
    __shared__ float hs[64][65];
    __shared__ float Wc[64][64];
    int tid = threadIdx.x;
    int n0 = blockIdx.x * 64;
    int chunk = blockIdx.y;  // 0..7: W2 slice; 8: root2

    for (int j = tid; j < 64 * 64; j += 256) {
        int nl = j >> 6, i = j & 63;
        int n = n0 + nl;
        hs[nl][i] = (n < NN) ? g_h[n * 64 + i] : 0.f;
    }
    for (int j = tid; j < 64 * 64; j += 256) {
        int i = j >> 6, o = j & 63;
        Wc[i][o] = (chunk < 8) ? W2[chunk * 4096 + i * 64 + o] : root2[i * 64 + o];
    }
    __syncthreads();

    int oc = tid & 31;
    int g  = tid >> 5;
    float a0[8], a1[8];
#pragma unroll
    for (int r = 0; r < 8; r++) { a0[r] = 0.f; a1[r] = 0.f; }
#pragma unroll
    for (int i = 0; i < 64; i++) {
        float w0 = Wc[i][oc], w1 = Wc[i][oc + 32];
#pragma unroll
        for (int r = 0; r < 8; r++) {
            float xv = hs[g * 8 + r][i];
            a0[r] += xv * w0;
            a1[r] += xv * w1;
        }
    }
#pragma unroll
    for (int r = 0; r < 8; r++) {
        int n = n0 + g * 8 + r;
        if (n >= NN) break;
        if (chunk < 8) {
            g_z[(size_t)n * 512 + chunk * 64 + oc]      = a0[r];
            g_z[(size_t)n * 512 + chunk * 64 + oc + 32] = a1[r];
        } else {
            g_aux[n * 128 + oc]      = a0[r];
            g_aux[n * 128 + oc + 32] = a1[r];
        }
    }
}

// ---------------- edge pass: warp per edge, trilinear-combine z[src], scatter to agg[dst] ----------------
__global__ void __launch_bounds__(256) edge_kernel(const int* __restrict__ ei,
                                                   const float* __restrict__ ea,
                                                   int do_cnt) {
    int e = (blockIdx.x * 256 + threadIdx.x) >> 5;
    if (e >= EE) return;
    int lane = threadIdx.x & 31;
    int src = __ldg(&ei[e]);
    int dst = __ldg(&ei[EE + e]);
    float u0 = __ldg(&ea[e * 3 + 0]);
    float u1 = __ldg(&ea[e * 3 + 1]);
    float u2 = __ldg(&ea[e * 3 + 2]);
    float v0 = 1.f - u0, v1 = 1.f - u1, v2 = 1.f - u2;
    float b[8];
    b[0] = v0 * v1 * v2; b[1] = u0 * v1 * v2;
    b[2] = v0 * u1 * v2; b[3] = u0 * u1 * v2;
    b[4] = v0 * v1 * u2; b[5] = u0 * v1 * u2;
    b[6] = v0 * u1 * u2; b[7] = u0 * u1 * u2;

    const float2* zp = (const float2*)(g_z + (size_t)src * 512) + lane;
    float ax = 0.f, ay = 0.f;
#pragma unroll
    for (int k = 0; k < 8; k++) {
        float2 v = __ldg(zp + k * 32);
        ax += b[k] * v.x;
        ay += b[k] * v.y;
    }
    float* ap = g_agg + (size_t)dst * 64 + 2 * lane;
    atomicAdd(ap, ax);
    atomicAdd(ap + 1, ay);
    if (do_cnt && lane == 0) atomicAdd(&g_cnt[dst], 1.f);
}

// ---------------- finish1: h_pre = agg/cnt + root1term; BN stats for h (slot0) and skip (slot1) ----------------
__global__ void __launch_bounds__(256) finish1_kernel() {
    int o = threadIdx.x & 63;
    int g = threadIdx.x >> 6;  // 0..3
    float sh = 0.f, qh = 0.f, ss = 0.f, qs = 0.f;
    for (int n = blockIdx.x * 4 + g; n < NN; n += gridDim.x * 4) {
        float inv = 1.0f / fmaxf(g_cnt[n], 1.0f);
        float h = g_agg[n * 64 + o] * inv + g_aux[n * 128 + o];
        g_h[n * 64 + o] = h;
        sh += h; qh += h * h;
        float s = g_aux[n * 128 + 64 + o];
        ss += s; qs += s * s;
    }
    __shared__ float red[4][256];
    red[0][threadIdx.x] = sh; red[1][threadIdx.x] = qh;
    red[2][threadIdx.x] = ss; red[3][threadIdx.x] = qs;
    __syncthreads();
    if (g == 0) {
        float t0 = red[0][o] + red[0][64 + o] + red[0][128 + o] + red[0][192 + o];
        float t1 = red[1][o] + red[1][64 + o] + red[1][128 + o] + red[1][192 + o];
        float t2 = red[2][o] + red[2][64 + o] + red[2][128 + o] + red[2][192 + o];
        float t3 = red[3][o] + red[3][64 + o] + red[3][128 + o] + red[3][192 + o];
        atomicAdd(&g_sum[o], t0);
        atomicAdd(&g_sq[o], t1);
        atomicAdd(&g_sum[64 + o], t2);
        atomicAdd(&g_sq[64 + o], t3);
    }
}

// ---------------- finish2: h2_pre = agg/cnt + root2term; BN stats slot2 ----------------
__global__ void __launch_bounds__(256) finish2_kernel() {
    int o = threadIdx.x & 63;
    int g = threadIdx.x >> 6;
    float sh = 0.f, qh = 0.f;
    for (int n = blockIdx.x * 4 + g; n < NN; n += gridDim.x * 4) {
        float inv = 1.0f / fmaxf(g_cnt[n], 1.0f);
        float h = g_agg[n * 64 + o] * inv + g_aux[n * 128 + o];
        g_h[n * 64 + o] = h;
        sh += h; qh += h * h;
    }
    __shared__ float red[2][256];
    red[0][threadIdx.x] = sh; red[1][threadIdx.x] = qh;
    __syncthreads();
    if (g == 0) {
        float t0 = red[0][o] + red[0][64 + o] + red[0][128 + o] + red[0][192 + o];
        float t1 = red[1][o] + red[1][64 + o] + red[1][128 + o] + red[1][192 + o];
        atomicAdd(&g_sum[128 + o], t0);
        atomicAdd(&g_sq[128 + o], t1);
    }
}

// ---------------- statfin: per-column scale/shift from sums ----------------
__global__ void statfin_kernel(int slot, const float* __restrict__ gamma,
                               const float* __restrict__ beta) {
    int o = threadIdx.x;
    if (o >= 64) return;
    float mu  = g_sum[slot * 64 + o] * (1.0f / NN);
    float var = g_sq[slot * 64 + o] * (1.0f / NN) - mu * mu;
    float sc  = gamma[o] * rsqrtf(var + 1e-5f);
    g_scale[slot * 64 + o] = sc;
    g_shift[slot * 64 + o] = beta[o] - mu * sc;
}

// ---------------- bn+elu on h (in place) ----------------
__global__ void __launch_bounds__(256) bnelu_kernel() {
    int i = blockIdx.x * 256 + threadIdx.x;
    if (i >= NN * 64) return;
    int o = i & 63;
    float v = g_h[i] * g_scale[o] + g_shift[o];
    g_h[i] = (v > 0.f) ? v : expm1f(v);
}

// ---------------- final: out = elu( BN(h2) + BN(skip) ) ----------------
__global__ void __launch_bounds__(256) final_kernel(float* __restrict__ out) {
    int i = blockIdx.x * 256 + threadIdx.x;
    if (i >= NN * 64) return;
    int o = i & 63;
    int n = i >> 6;
    float h2 = g_h[i] * g_scale[128 + o] + g_shift[128 + o];
    float s  = g_aux[n * 128 + 64 + o] * g_scale[64 + o] + g_shift[64 + o];
    float v = h2 + s;
    out[i] = (v > 0.f) ? v : expm1f(v);
}

extern "C" void kernel_launch(void* const* d_in, const int* in_sizes, int n_in,
                              void* d_out, int out_size) {
    const float* x     = (const float*)d_in[0];
    const int*   ei    = (const int*)d_in[1];
    const float* ea    = (const float*)d_in[2];
    const float* W1    = (const float*)d_in[3];
    const float* root1 = (const float*)d_in[4];
    const float* g1    = (const float*)d_in[5];
    const float* b1    = (const float*)d_in[6];
    const float* W2    = (const float*)d_in[7];
    const float* root2 = (const float*)d_in[8];
    const float* g2    = (const float*)d_in[9];
    const float* b2    = (const float*)d_in[10];
    const float* Wsk   = (const float*)d_in[11];
    const float* gsk   = (const float*)d_in[12];
    const float* bsk   = (const float*)d_in[13];
    float* out = (float*)d_out;

    void *agg_p, *cnt_p, *sum_p, *sq_p;
    cudaGetSymbolAddress(&agg_p, g_agg);
    cudaGetSymbolAddress(&cnt_p, g_cnt);
    cudaGetSymbolAddress(&sum_p, g_sum);
    cudaGetSymbolAddress(&sq_p, g_sq);

    cudaMemsetAsync(agg_p, 0, sizeof(float) * (size_t)NN * 64, 0);
    cudaMemsetAsync(cnt_p, 0, sizeof(float) * NN, 0);
    cudaMemsetAsync(sum_p, 0, sizeof(float) * 192, 0);
    cudaMemsetAsync(sq_p, 0, sizeof(float) * 192, 0);

    // ---- layer 1 ----
    dim3 zg1((NN + 63) / 64, 10);
    z1_kernel<<<zg1, 256>>>(x, W1, root1, Wsk);
    edge_kernel<<<EE / 8, 256>>>(ei, ea, 1);
    finish1_kernel<<<512, 256>>>();
    statfin_kernel<<<1, 64>>>(0, g1, b1);
    statfin_kernel<<<1, 64>>>(1, gsk, bsk);
    bnelu_kernel<<<(NN * 64 + 255) / 256, 256>>>();

    // ---- layer 2 ----
    dim3 zg2((NN + 63) / 64, 9);
    z2_kernel<<<zg2, 256>>>(W2, root2);
    cudaMemsetAsync(agg_p, 0, sizeof(float) * (size_t)NN * 64, 0);
    edge_kernel<<<EE / 8, 256>>>(ei, ea, 0);  // counts reused from layer 1 (same dst)
    finish2_kernel<<<512, 256>>>();
    statfin_kernel<<<1, 64>>>(2, g2, b2);
    final_kernel<<<(NN * 64 + 255) / 256, 256>>>(out);
}

// round 2
// speedup vs baseline: 1.1997x; 1.1997x over previous
#include <cuda_runtime.h>
#include <cuda_fp16.h>
#include <math.h>

#define NN 100000
#define EE 1600000

// ---- scratch (device globals; no allocation allowed) ----
__device__ float g_z[(size_t)NN * 512];    // fp32 z[n][k][o] (204.8 MB), staging
__device__ uint4 g_zh4[(size_t)NN * 64];   // fp16 z[n][slot][k] packed (102.4 MB), 16B aligned
__device__ float g_aux[(size_t)NN * 128];  // [n][0:64]=root term, [n][64:128]=skip pre-BN
__device__ float g_agg[(size_t)NN * 64];   // edge aggregation target (25.6 MB, L2-resident)
__device__ float g_h[(size_t)NN * 64];     // h (layer1 act) then h2 pre-BN
__device__ float g_cnt[NN];
__device__ float g_sum[192];               // BN col sums: slot0=h1, slot1=skip, slot2=h2
__device__ float g_sq[192];
__device__ float g_scale[192];
__device__ float g_shift[192];

// ---------------- z1: out = x @ [W1(8x32x64) | root1 | W_skip] ----------------
__global__ void __launch_bounds__(256) z1_kernel(const float* __restrict__ x,
                                                 const float* __restrict__ W1,
                                                 const float* __restrict__ root1,
                                                 const float* __restrict__ Wskip) {
    __shared__ float xs[64][33];
    __shared__ float Wc[32][64];
    int tid = threadIdx.x;
    int n0 = blockIdx.x * 64;
    int chunk = blockIdx.y;  // 0..7: W1 slice k; 8: root1; 9: W_skip

    for (int j = tid; j < 64 * 32; j += 256) {
        int nl = j >> 5, i = j & 31;
        int n = n0 + nl;
        xs[nl][i] = (n < NN) ? x[n * 32 + i] : 0.f;
    }
    for (int j = tid; j < 32 * 64; j += 256) {
        int i = j >> 6, o = j & 63;
        float w;
        if (chunk < 8)       w = W1[chunk * 2048 + i * 64 + o];
        else if (chunk == 8) w = root1[i * 64 + o];
        else                 w = Wskip[i * 64 + o];
        Wc[i][o] = w;
    }
    __syncthreads();

    int oc = tid & 31;
    int g  = tid >> 5;
    float a0[8], a1[8];
#pragma unroll
    for (int r = 0; r < 8; r++) { a0[r] = 0.f; a1[r] = 0.f; }
#pragma unroll
    for (int i = 0; i < 32; i++) {
        float w0 = Wc[i][oc], w1 = Wc[i][oc + 32];
#pragma unroll
        for (int r = 0; r < 8; r++) {
            float xv = xs[g * 8 + r][i];
            a0[r] += xv * w0;
            a1[r] += xv * w1;
        }
    }
#pragma unroll
    for (int r = 0; r < 8; r++) {
        int n = n0 + g * 8 + r;
        if (n >= NN) break;
        if (chunk < 8) {
            g_z[(size_t)n * 512 + chunk * 64 + oc]      = a0[r];
            g_z[(size_t)n * 512 + chunk * 64 + oc + 32] = a1[r];
        } else if (chunk == 8) {
            g_aux[n * 128 + oc]      = a0[r];
            g_aux[n * 128 + oc + 32] = a1[r];
        } else {
            g_aux[n * 128 + 64 + oc]      = a0[r];
            g_aux[n * 128 + 64 + oc + 32] = a1[r];
        }
    }
}

// ---------------- z2: out = h @ [W2(8x64x64) | root2] ----------------
__global__ void __launch_bounds__(256) z2_kernel(const float* __restrict__ W2,
                                                 const float* __restrict__ root2) {
    __shared__ float hs[64][65];
    __shared__ float Wc[64][64];
    int tid = threadIdx.x;
    int n0 = blockIdx.x * 64;
    int chunk = blockIdx.y;  // 0..7: W2 slice; 8: root2

    for (int j = tid; j < 64 * 64; j += 256) {
        int nl = j >> 6, i = j & 63;
        int n = n0 + nl;
        hs[nl][i] = (n < NN) ? g_h[n * 64 + i] : 0.f;
    }
    for (int j = tid; j < 64 * 64; j += 256) {
        int i = j >> 6, o = j & 63;
        Wc[i][o] = (chunk < 8) ? W2[chunk * 4096 + i * 64 + o] : root2[i * 64 + o];
    }
    __syncthreads();

    int oc = tid & 31;
    int g  = tid >> 5;
    float a0[8], a1[8];
#pragma unroll
    for (int r = 0; r < 8; r++) { a0[r] = 0.f; a1[r] = 0.f; }
#pragma unroll
    for (int i = 0; i < 64; i++) {
        float w0 = Wc[i][oc], w1 = Wc[i][oc + 32];
#pragma unroll
        for (int r = 0; r < 8; r++) {
            float xv = hs[g * 8 + r][i];
            a0[r] += xv * w0;
            a1[r] += xv * w1;
        }
    }
#pragma unroll
    for (int r = 0; r < 8; r++) {
        int n = n0 + g * 8 + r;
        if (n >= NN) break;
        if (chunk < 8) {
            g_z[(size_t)n * 512 + chunk * 64 + oc]      = a0[r];
            g_z[(size_t)n * 512 + chunk * 64 + oc + 32] = a1[r];
        } else {
            g_aux[n * 128 + oc]      = a0[r];
            g_aux[n * 128 + oc + 32] = a1[r];
        }
    }
}

// ---------------- transpose/convert: g_z fp32 [n][k][o] -> g_zh4 fp16 [n][slot][k] ----------------
// slot s (0..63) holds o = 2*s     for s in [0,32)
//                      o = 2*(s-32)+1 for s in [32,64)
// so edge lane l reads slot l  -> o=2l   and slot 32+l -> o=2l+1 (both coalesced 512B rounds)
__global__ void __launch_bounds__(256) trans_kernel() {
    int n = blockIdx.x * 8 + (threadIdx.x >> 5);
    if (n >= NN) return;
    int l = threadIdx.x & 31;
    const float* zr = g_z + (size_t)n * 512;
    uint4* dp = g_zh4 + (size_t)n * 64;
#pragma unroll
    for (int r = 0; r < 2; r++) {
        int o = 2 * l + r;
        __align__(16) __half hs[8];
#pragma unroll
        for (int k = 0; k < 8; k++) hs[k] = __float2half(zr[k * 64 + o]);
        dp[r * 32 + l] = *reinterpret_cast<uint4*>(hs);
    }
}

// ---------------- edge pass: warp/edge, fp16 gather + trilinear combine + vector red ----------------
__device__ __forceinline__ float dot8(uint4 v, const float* b) {
    const __half2* h = reinterpret_cast<const __half2*>(&v);
    float s = 0.f;
#pragma unroll
    for (int i = 0; i < 4; i++) {
        float2 f = __half22float2(h[i]);
        s += b[2 * i] * f.x + b[2 * i + 1] * f.y;
    }
    return s;
}

__device__ __forceinline__ void red_add_v2(float* p, float a, float b) {
    asm volatile("red.global.add.v2.f32 [%0], {%1, %2};"
                 :: "l"(p), "f"(a), "f"(b) : "memory");
}

__global__ void __launch_bounds__(256) edge_kernel(const int* __restrict__ ei,
                                                   const float* __restrict__ ea,
                                                   int do_cnt) {
    int e = (blockIdx.x * 256 + threadIdx.x) >> 5;
    if (e >= EE) return;
    int lane = threadIdx.x & 31;
    int src = __ldg(&ei[e]);
    int dst = __ldg(&ei[EE + e]);
    float u0 = __ldg(&ea[e * 3 + 0]);
    float u1 = __ldg(&ea[e * 3 + 1]);
    float u2 = __ldg(&ea[e * 3 + 2]);
    float v0 = 1.f - u0, v1 = 1.f - u1, v2 = 1.f - u2;
    float b[8];
    b[0] = v0 * v1 * v2; b[1] = u0 * v1 * v2;
    b[2] = v0 * u1 * v2; b[3] = u0 * u1 * v2;
    b[4] = v0 * v1 * u2; b[5] = u0 * v1 * u2;
    b[6] = v0 * u1 * u2; b[7] = u0 * u1 * u2;

    const uint4* zr = g_zh4 + (size_t)src * 64;
    uint4 A = __ldg(zr + lane);        // o = 2*lane
    uint4 B = __ldg(zr + 32 + lane);   // o = 2*lane + 1
    float s0 = dot8(A, b);
    float s1 = dot8(B, b);
    red_add_v2(g_agg + (size_t)dst * 64 + 2 * lane, s0, s1);
    if (do_cnt && lane == 0) atomicAdd(&g_cnt[dst], 1.f);
}

// ---------------- finish1: h_pre = agg/cnt + root1term; BN stats slot0 (h) and slot1 (skip) ----------------
__global__ void __launch_bounds__(256) finish1_kernel() {
    int o = threadIdx.x & 63;
    int g = threadIdx.x >> 6;
    float sh = 0.f, qh = 0.f, ss = 0.f, qs = 0.f;
    for (int n = blockIdx.x * 4 + g; n < NN; n += gridDim.x * 4) {
        float inv = 1.0f / fmaxf(g_cnt[n], 1.0f);
        float h = g_agg[n * 64 + o] * inv + g_aux[n * 128 + o];
        g_h[n * 64 + o] = h;
        sh += h; qh += h * h;
        float s = g_aux[n * 128 + 64 + o];
        ss += s; qs += s * s;
    }
    __shared__ float red[4][256];
    red[0][threadIdx.x] = sh; red[1][threadIdx.x] = qh;
    red[2][threadIdx.x] = ss; red[3][threadIdx.x] = qs;
    __syncthreads();
    if (g == 0) {
        float t0 = red[0][o] + red[0][64 + o] + red[0][128 + o] + red[0][192 + o];
        float t1 = red[1][o] + red[1][64 + o] + red[1][128 + o] + red[1][192 + o];
        float t2 = red[2][o] + red[2][64 + o] + red[2][128 + o] + red[2][192 + o];
        float t3 = red[3][o] + red[3][64 + o] + red[3][128 + o] + red[3][192 + o];
        atomicAdd(&g_sum[o], t0);
        atomicAdd(&g_sq[o], t1);
        atomicAdd(&g_sum[64 + o], t2);
        atomicAdd(&g_sq[64 + o], t3);
    }
}

// ---------------- finish2: h2_pre = agg/cnt + root2term; BN stats slot2 ----------------
__global__ void __launch_bounds__(256) finish2_kernel() {
    int o = threadIdx.x & 63;
    int g = threadIdx.x >> 6;
    float sh = 0.f, qh = 0.f;
    for (int n = blockIdx.x * 4 + g; n < NN; n += gridDim.x * 4) {
        float inv = 1.0f / fmaxf(g_cnt[n], 1.0f);
        float h = g_agg[n * 64 + o] * inv + g_aux[n * 128 + o];
        g_h[n * 64 + o] = h;
        sh += h; qh += h * h;
    }
    __shared__ float red[2][256];
    red[0][threadIdx.x] = sh; red[1][threadIdx.x] = qh;
    __syncthreads();
    if (g == 0) {
        float t0 = red[0][o] + red[0][64 + o] + red[0][128 + o] + red[0][192 + o];
        float t1 = red[1][o] + red[1][64 + o] + red[1][128 + o] + red[1][192 + o];
        atomicAdd(&g_sum[128 + o], t0);
        atomicAdd(&g_sq[128 + o], t1);
    }
}

// ---------------- statfin: scale/shift for two slots in one launch ----------------
__global__ void statfin2_kernel(int slotA, const float* __restrict__ gA, const float* __restrict__ bA,
                                int slotB, const float* __restrict__ gB, const float* __restrict__ bB) {
    int t = threadIdx.x;
    if (t >= 128) return;
    int which = t >> 6;
    int o = t & 63;
    int slot = which ? slotB : slotA;
    if (slot < 0) return;
    const float* gamma = which ? gB : gA;
    const float* beta  = which ? bB : bA;
    float mu  = g_sum[slot * 64 + o] * (1.0f / NN);
    float var = g_sq[slot * 64 + o] * (1.0f / NN) - mu * mu;
    float sc  = gamma[o] * rsqrtf(var + 1e-5f);
    g_scale[slot * 64 + o] = sc;
    g_shift[slot * 64 + o] = beta[o] - mu * sc;
}

// ---------------- bn+elu on h (in place) ----------------
__global__ void __launch_bounds__(256) bnelu_kernel() {
    int i = blockIdx.x * 256 + threadIdx.x;
    if (i >= NN * 64) return;
    int o = i & 63;
    float v = g_h[i] * g_scale[o] + g_shift[o];
    g_h[i] = (v > 0.f) ? v : expm1f(v);
}

// ---------------- final: out = elu( BN(h2) + BN(skip) ) ----------------
__global__ void __launch_bounds__(256) final_kernel(float* __restrict__ out) {
    int i = blockIdx.x * 256 + threadIdx.x;
    if (i >= NN * 64) return;
    int o = i & 63;
    int n = i >> 6;
    float h2 = g_h[i] * g_scale[128 + o] + g_shift[128 + o];
    float s  = g_aux[n * 128 + 64 + o] * g_scale[64 + o] + g_shift[64 + o];
    float v = h2 + s;
    out[i] = (v > 0.f) ? v : expm1f(v);
}

extern "C" void kernel_launch(void* const* d_in, const int* in_sizes, int n_in,
                              void* d_out, int out_size) {
    const float* x     = (const float*)d_in[0];
    const int*   ei    = (const int*)d_in[1];
    const float* ea    = (const float*)d_in[2];
    const float* W1    = (const float*)d_in[3];
    const float* root1 = (const float*)d_in[4];
    const float* g1    = (const float*)d_in[5];
    const float* b1    = (const float*)d_in[6];
    const float* W2    = (const float*)d_in[7];
    const float* root2 = (const float*)d_in[8];
    const float* g2    = (const float*)d_in[9];
    const float* b2    = (const float*)d_in[10];
    const float* Wsk   = (const float*)d_in[11];
    const float* gsk   = (const float*)d_in[12];
    const float* bsk   = (const float*)d_in[13];
    float* out = (float*)d_out;

    void *agg_p, *cnt_p, *sum_p, *sq_p;
    cudaGetSymbolAddress(&agg_p, g_agg);
    cudaGetSymbolAddress(&cnt_p, g_cnt);
    cudaGetSymbolAddress(&sum_p, g_sum);
    cudaGetSymbolAddress(&sq_p, g_sq);

    cudaMemsetAsync(agg_p, 0, sizeof(float) * (size_t)NN * 64, 0);
    cudaMemsetAsync(cnt_p, 0, sizeof(float) * NN, 0);
    cudaMemsetAsync(sum_p, 0, sizeof(float) * 192, 0);
    cudaMemsetAsync(sq_p, 0, sizeof(float) * 192, 0);

    // ---- layer 1 ----
    dim3 zg1((NN + 63) / 64, 10);
    z1_kernel<<<zg1, 256>>>(x, W1, root1, Wsk);
    trans_kernel<<<(NN + 7) / 8, 256>>>();
    edge_kernel<<<EE / 8, 256>>>(ei, ea, 1);
    finish1_kernel<<<512, 256>>>();
    statfin2_kernel<<<1, 128>>>(0, g1, b1, 1, gsk, bsk);
    bnelu_kernel<<<(NN * 64 + 255) / 256, 256>>>();

    // ---- layer 2 ----
    dim3 zg2((NN + 63) / 64, 9);
    z2_kernel<<<zg2, 256>>>(W2, root2);
    trans_kernel<<<(NN + 7) / 8, 256>>>();
    cudaMemsetAsync(agg_p, 0, sizeof(float) * (size_t)NN * 64, 0);
    edge_kernel<<<EE / 8, 256>>>(ei, ea, 0);  // counts reused from layer 1 (same dst)
    finish2_kernel<<<512, 256>>>();
    statfin2_kernel<<<1, 128>>>(2, g2, b2, -1, g2, b2);
    final_kernel<<<(NN * 64 + 255) / 256, 256>>>(out);
}

// round 3
// speedup vs baseline: 1.4226x; 1.1858x over previous
#include <cuda_runtime.h>
#include <cuda_fp16.h>
#include <math.h>

#define NN 100000
#define EE 1600000

// ---- scratch (device globals; no allocation allowed) ----
__device__ __half g_zh[(size_t)NN * 512];   // fp16 z[n][k][o], o-pairs contiguous (102.4 MB)
__device__ float g_aux[(size_t)NN * 128];   // [n][0:64]=root term, [n][64:128]=skip pre-BN
__device__ float g_h[(size_t)NN * 64];      // h (layer1 act) then h2 pre-BN
__device__ int   g_deg[NN];
__device__ int   g_off[NN + 1];
__device__ int   g_cur[NN];
__device__ int   g_esrc[EE];                // src, sorted by dst
__device__ uint4 g_ebasis[EE];              // 8 fp16 basis weights, sorted by dst (25.6 MB)
__device__ float g_sum[192];                // BN sums: slot0=h1, slot1=skip, slot2=h2
__device__ float g_sq[192];
__device__ float g_scale[192];
__device__ float g_shift[192];

// ---------------- z1: [zh | aux] = x @ [W1(8x32x64) | root1 | W_skip] ----------------
__global__ void __launch_bounds__(256) z1_kernel(const float* __restrict__ x,
                                                 const float* __restrict__ W1,
                                                 const float* __restrict__ root1,
                                                 const float* __restrict__ Wskip) {
    __shared__ float xs[64][33];
    __shared__ float Wc[32][64];
    int tid = threadIdx.x;
    int n0 = blockIdx.x * 64;
    int chunk = blockIdx.y;  // 0..7: W1 slice k; 8: root1; 9: W_skip

    for (int j = tid; j < 64 * 32; j += 256) {
        int nl = j >> 5, i = j & 31;
        int n = n0 + nl;
        xs[nl][i] = (n < NN) ? x[n * 32 + i] : 0.f;
    }
    for (int j = tid; j < 32 * 64; j += 256) {
        int i = j >> 6, o = j & 63;
        float w;
        if (chunk < 8)       w = W1[chunk * 2048 + i * 64 + o];
        else if (chunk == 8) w = root1[i * 64 + o];
        else                 w = Wskip[i * 64 + o];
        Wc[i][o] = w;
    }
    __syncthreads();

    int oc = tid & 31;   // handles adjacent columns 2*oc, 2*oc+1
    int g  = tid >> 5;
    float a0[8], a1[8];
#pragma unroll
    for (int r = 0; r < 8; r++) { a0[r] = 0.f; a1[r] = 0.f; }
#pragma unroll
    for (int i = 0; i < 32; i++) {
        float w0 = Wc[i][2 * oc], w1 = Wc[i][2 * oc + 1];
#pragma unroll
        for (int r = 0; r < 8; r++) {
            float xv = xs[g * 8 + r][i];
            a0[r] += xv * w0;
            a1[r] += xv * w1;
        }
    }
#pragma unroll
    for (int r = 0; r < 8; r++) {
        int n = n0 + g * 8 + r;
        if (n >= NN) break;
        if (chunk < 8) {
            __half2* zp = reinterpret_cast<__half2*>(g_zh);
            zp[(size_t)n * 256 + chunk * 32 + oc] = __floats2half2_rn(a0[r], a1[r]);
        } else if (chunk == 8) {
            reinterpret_cast<float2*>(g_aux)[n * 64 + oc] = make_float2(a0[r], a1[r]);
        } else {
            reinterpret_cast<float2*>(g_aux)[n * 64 + 32 + oc] = make_float2(a0[r], a1[r]);
        }
    }
}

// ---------------- z2: [zh | aux] = h @ [W2(8x64x64) | root2] ----------------
__global__ void __launch_bounds__(256) z2_kernel(const float* __restrict__ W2,
                                                 const float* __restrict__ root2) {
    __shared__ float hs[64][65];
    __shared__ float Wc[64][64];
    int tid = threadIdx.x;
    int n0 = blockIdx.x * 64;
    int chunk = blockIdx.y;  // 0..7: W2 slice; 8: root2

    for (int j = tid; j < 64 * 64; j += 256) {
        int nl = j >> 6, i = j & 63;
        int n = n0 + nl;
        hs[nl][i] = (n < NN) ? g_h[n * 64 + i] : 0.f;
    }
    for (int j = tid; j < 64 * 64; j += 256) {
        int i = j >> 6, o = j & 63;
        Wc[i][o] = (chunk < 8) ? W2[chunk * 4096 + i * 64 + o] : root2[i * 64 + o];
    }
    __syncthreads();

    int oc = tid & 31;
    int g  = tid >> 5;
    float a0[8], a1[8];
#pragma unroll
    for (int r = 0; r < 8; r++) { a0[r] = 0.f; a1[r] = 0.f; }
#pragma unroll
    for (int i = 0; i < 64; i++) {
        float w0 = Wc[i][2 * oc], w1 = Wc[i][2 * oc + 1];
#pragma unroll
        for (int r = 0; r < 8; r++) {
            float xv = hs[g * 8 + r][i];
            a0[r] += xv * w0;
            a1[r] += xv * w1;
        }
    }
#pragma unroll
    for (int r = 0; r < 8; r++) {
        int n = n0 + g * 8 + r;
        if (n >= NN) break;
        if (chunk < 8) {
            __half2* zp = reinterpret_cast<__half2*>(g_zh);
            zp[(size_t)n * 256 + chunk * 32 + oc] = __floats2half2_rn(a0[r], a1[r]);
        } else {
            reinterpret_cast<float2*>(g_aux)[n * 64 + oc] = make_float2(a0[r], a1[r]);
        }
    }
}

// ---------------- CSR build: histogram ----------------
__global__ void __launch_bounds__(256) hist_kernel(const int* __restrict__ ei) {
    int e = blockIdx.x * 256 + threadIdx.x;
    if (e >= EE) return;
    atomicAdd(&g_deg[__ldg(&ei[EE + e])], 1);
}

// ---------------- CSR build: single-block exclusive scan (shfl-based) ----------------
__global__ void __launch_bounds__(1024) scan_kernel() {
    __shared__ int wsum[32];
    __shared__ int chunk_total;
    int tid = threadIdx.x, lane = tid & 31, wid = tid >> 5;
    int base = 0;
    for (int start = 0; start < NN; start += 1024) {
        int i = start + tid;
        int v = (i < NN) ? g_deg[i] : 0;
        int inc = v;
#pragma unroll
        for (int d = 1; d < 32; d <<= 1) {
            int t = __shfl_up_sync(0xffffffffu, inc, d);
            if (lane >= d) inc += t;
        }
        if (lane == 31) wsum[wid] = inc;
        __syncthreads();
        if (wid == 0) {
            int w = wsum[lane];
            int winc = w;
#pragma unroll
            for (int d = 1; d < 32; d <<= 1) {
                int t = __shfl_up_sync(0xffffffffu, winc, d);
                if (lane >= d) winc += t;
            }
            wsum[lane] = winc - w;
            if (lane == 31) chunk_total = winc;
        }
        __syncthreads();
        int excl = base + wsum[wid] + inc - v;
        if (i < NN) { g_off[i] = excl; g_cur[i] = excl; }
        base += chunk_total;
        __syncthreads();
    }
    if (tid == 0) g_off[NN] = base;
}

// ---------------- CSR build: scatter src + fp16 basis, sorted by dst ----------------
__global__ void __launch_bounds__(256) scatter_kernel(const int* __restrict__ ei,
                                                      const float* __restrict__ ea) {
    int e = blockIdx.x * 256 + threadIdx.x;
    if (e >= EE) return;
    int src = __ldg(&ei[e]);
    int dst = __ldg(&ei[EE + e]);
    float u0 = __ldg(&ea[e * 3 + 0]);
    float u1 = __ldg(&ea[e * 3 + 1]);
    float u2 = __ldg(&ea[e * 3 + 2]);
    float v0 = 1.f - u0, v1 = 1.f - u1, v2 = 1.f - u2;
    __align__(16) __half hb[8];
    hb[0] = __float2half(v0 * v1 * v2); hb[1] = __float2half(u0 * v1 * v2);
    hb[2] = __float2half(v0 * u1 * v2); hb[3] = __float2half(u0 * u1 * v2);
    hb[4] = __float2half(v0 * v1 * u2); hb[5] = __float2half(u0 * v1 * u2);
    hb[6] = __float2half(v0 * u1 * u2); hb[7] = __float2half(u0 * u1 * u2);
    int pos = atomicAdd(&g_cur[dst], 1);
    g_esrc[pos] = src;
    g_ebasis[pos] = *reinterpret_cast<uint4*>(hb);
}

// ---------------- agg: warp per dst node; gather+combine+finish+BN stats fused ----------------
__global__ void __launch_bounds__(256) agg_kernel(int layer1) {
    __shared__ float s_sum[128], s_sq[128];
    for (int j = threadIdx.x; j < 128; j += 256) { s_sum[j] = 0.f; s_sq[j] = 0.f; }
    __syncthreads();

    int wid = threadIdx.x >> 5;
    int lane = threadIdx.x & 31;
    int n = blockIdx.x * 8 + wid;
    if (n < NN) {
        int start = __ldg(&g_off[n]);
        int end   = __ldg(&g_off[n + 1]);
        float acc0 = 0.f, acc1 = 0.f;
        const __half2* zb = reinterpret_cast<const __half2*>(g_zh);
        for (int e = start; e < end; e++) {
            int src = __ldg(&g_esrc[e]);
            uint4 bw = __ldg(&g_ebasis[e]);
            const __half2* bh = reinterpret_cast<const __half2*>(&bw);
            float2 b0 = __half22float2(bh[0]);
            float2 b1 = __half22float2(bh[1]);
            float2 b2 = __half22float2(bh[2]);
            float2 b3 = __half22float2(bh[3]);
            const __half2* zp = zb + (size_t)src * 256 + lane;
            float2 f;
            f = __half22float2(__ldg(zp +   0)); acc0 += b0.x * f.x; acc1 += b0.x * f.y;
            f = __half22float2(__ldg(zp +  32)); acc0 += b0.y * f.x; acc1 += b0.y * f.y;
            f = __half22float2(__ldg(zp +  64)); acc0 += b1.x * f.x; acc1 += b1.x * f.y;
            f = __half22float2(__ldg(zp +  96)); acc0 += b1.y * f.x; acc1 += b1.y * f.y;
            f = __half22float2(__ldg(zp + 128)); acc0 += b2.x * f.x; acc1 += b2.x * f.y;
            f = __half22float2(__ldg(zp + 160)); acc0 += b2.y * f.x; acc1 += b2.y * f.y;
            f = __half22float2(__ldg(zp + 192)); acc0 += b3.x * f.x; acc1 += b3.x * f.y;
            f = __half22float2(__ldg(zp + 224)); acc0 += b3.y * f.x; acc1 += b3.y * f.y;
        }
        int deg = end - start;
        float inv = 1.0f / (float)(deg > 0 ? deg : 1);
        float2 rt = reinterpret_cast<const float2*>(g_aux)[n * 64 + lane];
        float h0 = acc0 * inv + rt.x;
        float h1 = acc1 * inv + rt.y;
        reinterpret_cast<float2*>(g_h)[n * 32 + lane] = make_float2(h0, h1);
        int o0 = 2 * lane;
        atomicAdd(&s_sum[o0], h0);     atomicAdd(&s_sq[o0], h0 * h0);
        atomicAdd(&s_sum[o0 + 1], h1); atomicAdd(&s_sq[o0 + 1], h1 * h1);
        if (layer1) {
            float2 sk = reinterpret_cast<const float2*>(g_aux)[n * 64 + 32 + lane];
            atomicAdd(&s_sum[64 + o0], sk.x);     atomicAdd(&s_sq[64 + o0], sk.x * sk.x);
            atomicAdd(&s_sum[64 + o0 + 1], sk.y); atomicAdd(&s_sq[64 + o0 + 1], sk.y * sk.y);
        }
    }
    __syncthreads();
    int slotbase = layer1 ? 0 : 128;
    for (int j = threadIdx.x; j < 64; j += 256) {
        atomicAdd(&g_sum[slotbase + j], s_sum[j]);
        atomicAdd(&g_sq[slotbase + j], s_sq[j]);
    }
    if (layer1) {
        for (int j = threadIdx.x; j < 64; j += 256) {
            atomicAdd(&g_sum[64 + j], s_sum[64 + j]);
            atomicAdd(&g_sq[64 + j], s_sq[64 + j]);
        }
    }
}

// ---------------- statfin: scale/shift for up to two slots in one launch ----------------
__global__ void statfin2_kernel(int slotA, const float* __restrict__ gA, const float* __restrict__ bA,
                                int slotB, const float* __restrict__ gB, const float* __restrict__ bB) {
    int t = threadIdx.x;
    if (t >= 128) return;
    int which = t >> 6;
    int o = t & 63;
    int slot = which ? slotB : slotA;
    if (slot < 0) return;
    const float* gamma = which ? gB : gA;
    const float* beta  = which ? bB : bA;
    float mu  = g_sum[slot * 64 + o] * (1.0f / NN);
    float var = g_sq[slot * 64 + o] * (1.0f / NN) - mu * mu;
    float sc  = gamma[o] * rsqrtf(var + 1e-5f);
    g_scale[slot * 64 + o] = sc;
    g_shift[slot * 64 + o] = beta[o] - mu * sc;
}

// ---------------- bn+elu on h (in place) ----------------
__global__ void __launch_bounds__(256) bnelu_kernel() {
    int i = blockIdx.x * 256 + threadIdx.x;
    if (i >= NN * 64) return;
    int o = i & 63;
    float v = g_h[i] * g_scale[o] + g_shift[o];
    g_h[i] = (v > 0.f) ? v : expm1f(v);
}

// ---------------- final: out = elu( BN(h2) + BN(skip) ) ----------------
__global__ void __launch_bounds__(256) final_kernel(float* __restrict__ out) {
    int i = blockIdx.x * 256 + threadIdx.x;
    if (i >= NN * 64) return;
    int o = i & 63;
    int n = i >> 6;
    float h2 = g_h[i] * g_scale[128 + o] + g_shift[128 + o];
    float s  = g_aux[n * 128 + 64 + o] * g_scale[64 + o] + g_shift[64 + o];
    float v = h2 + s;
    out[i] = (v > 0.f) ? v : expm1f(v);
}

extern "C" void kernel_launch(void* const* d_in, const int* in_sizes, int n_in,
                              void* d_out, int out_size) {
    const float* x     = (const float*)d_in[0];
    const int*   ei    = (const int*)d_in[1];
    const float* ea    = (const float*)d_in[2];
    const float* W1    = (const float*)d_in[3];
    const float* root1 = (const float*)d_in[4];
    const float* g1    = (const float*)d_in[5];
    const float* b1    = (const float*)d_in[6];
    const float* W2    = (const float*)d_in[7];
    const float* root2 = (const float*)d_in[8];
    const float* g2    = (const float*)d_in[9];
    const float* b2    = (const float*)d_in[10];
    const float* Wsk   = (const float*)d_in[11];
    const float* gsk   = (const float*)d_in[12];
    const float* bsk   = (const float*)d_in[13];
    float* out = (float*)d_out;

    void *deg_p, *sum_p, *sq_p;
    cudaGetSymbolAddress(&deg_p, g_deg);
    cudaGetSymbolAddress(&sum_p, g_sum);
    cudaGetSymbolAddress(&sq_p, g_sq);

    cudaMemsetAsync(deg_p, 0, sizeof(int) * NN, 0);
    cudaMemsetAsync(sum_p, 0, sizeof(float) * 192, 0);
    cudaMemsetAsync(sq_p, 0, sizeof(float) * 192, 0);

    // ---- CSR build (shared by both layers) ----
    hist_kernel<<<(EE + 255) / 256, 256>>>(ei);
    scan_kernel<<<1, 1024>>>();
    scatter_kernel<<<(EE + 255) / 256, 256>>>(ei, ea);

    // ---- layer 1 ----
    dim3 zg1((NN + 63) / 64, 10);
    z1_kernel<<<zg1, 256>>>(x, W1, root1, Wsk);
    agg_kernel<<<(NN + 7) / 8, 256>>>(1);
    statfin2_kernel<<<1, 128>>>(0, g1, b1, 1, gsk, bsk);
    bnelu_kernel<<<(NN * 64 + 255) / 256, 256>>>();

    // ---- layer 2 ----
    dim3 zg2((NN + 63) / 64, 9);
    z2_kernel<<<zg2, 256>>>(W2, root2);
    agg_kernel<<<(NN + 7) / 8, 256>>>(0);
    statfin2_kernel<<<1, 128>>>(2, g2, b2, -1, g2, b2);
    final_kernel<<<(NN * 64 + 255) / 256, 256>>>(out);
}

// round 4
// speedup vs baseline: 2.1780x; 1.5310x over previous
#include <cuda_runtime.h>
#include <cuda_fp16.h>
#include <math.h>

#define NN 100000
#define EE 1600000

typedef unsigned long long ull;

// ---- scratch (device globals; no allocation allowed) ----
__device__ float g_A[(size_t)NN * 512];    // basis-weighted feature agg A[n][k*C+i] (204.8 MB max)
__device__ float g_aux[(size_t)NN * 128];  // [n][64:128] = skip pre-BN (stride 128, offset 64)
__device__ float g_h[(size_t)NN * 64];     // h (layer1 act) then h2 pre-BN
__device__ int   g_deg[NN];
__device__ int   g_off[NN + 1];
__device__ int   g_cur[NN];
__device__ int   g_esrc[EE];               // src, sorted by dst
__device__ uint4 g_ebasis[EE];             // 8 fp16 basis weights, sorted by dst (25.6 MB)
__device__ float g_sum[192];               // BN sums: slot0=h1, slot1=skip, slot2=h2
__device__ float g_sq[192];
__device__ float g_scale[192];
__device__ float g_shift[192];

// ---- packed f32x2 helpers (sm_10x) ----
__device__ __forceinline__ ull pk2(float x, float y) {
    ull r; asm("mov.b64 %0, {%1, %2};" : "=l"(r) : "f"(x), "f"(y)); return r;
}
__device__ __forceinline__ void fma2(ull& d, ull a, ull b) {
    asm("fma.rn.f32x2 %0, %1, %2, %3;" : "=l"(d) : "l"(a), "l"(b), "l"(d));
}
__device__ __forceinline__ float2 upk2(ull v) {
    float2 f; asm("mov.b64 {%0, %1}, %2;" : "=f"(f.x), "=f"(f.y) : "l"(v)); return f;
}

// ---------------- CSR build: histogram ----------------
__global__ void __launch_bounds__(256) hist_kernel(const int* __restrict__ ei) {
    int e = blockIdx.x * 256 + threadIdx.x;
    if (e >= EE) return;
    atomicAdd(&g_deg[__ldg(&ei[EE + e])], 1);
}

// ---------------- CSR build: single-block exclusive scan ----------------
__global__ void __launch_bounds__(1024) scan_kernel() {
    __shared__ int wsum[32];
    __shared__ int chunk_total;
    int tid = threadIdx.x, lane = tid & 31, wid = tid >> 5;
    int base = 0;
    for (int start = 0; start < NN; start += 1024) {
        int i = start + tid;
        int v = (i < NN) ? g_deg[i] : 0;
        int inc = v;
#pragma unroll
        for (int d = 1; d < 32; d <<= 1) {
            int t = __shfl_up_sync(0xffffffffu, inc, d);
            if (lane >= d) inc += t;
        }
        if (lane == 31) wsum[wid] = inc;
        __syncthreads();
        if (wid == 0) {
            int w = wsum[lane];
            int winc = w;
#pragma unroll
            for (int d = 1; d < 32; d <<= 1) {
                int t = __shfl_up_sync(0xffffffffu, winc, d);
                if (lane >= d) winc += t;
            }
            wsum[lane] = winc - w;
            if (lane == 31) chunk_total = winc;
        }
        __syncthreads();
        int excl = base + wsum[wid] + inc - v;
        if (i < NN) { g_off[i] = excl; g_cur[i] = excl; }
        base += chunk_total;
        __syncthreads();
    }
    if (tid == 0) g_off[NN] = base;
}

// ---------------- CSR build: scatter src + fp16 basis ----------------
__global__ void __launch_bounds__(256) scatter_kernel(const int* __restrict__ ei,
                                                      const float* __restrict__ ea) {
    int e = blockIdx.x * 256 + threadIdx.x;
    if (e >= EE) return;
    int src = __ldg(&ei[e]);
    int dst = __ldg(&ei[EE + e]);
    float u0 = __ldg(&ea[e * 3 + 0]);
    float u1 = __ldg(&ea[e * 3 + 1]);
    float u2 = __ldg(&ea[e * 3 + 2]);
    float v0 = 1.f - u0, v1 = 1.f - u1, v2 = 1.f - u2;
    __align__(16) __half hb[8];
    hb[0] = __float2half(v0 * v1 * v2); hb[1] = __float2half(u0 * v1 * v2);
    hb[2] = __float2half(v0 * u1 * v2); hb[3] = __float2half(u0 * u1 * v2);
    hb[4] = __float2half(v0 * v1 * u2); hb[5] = __float2half(u0 * v1 * u2);
    hb[6] = __float2half(v0 * u1 * u2); hb[7] = __float2half(u0 * u1 * u2);
    int pos = atomicAdd(&g_cur[dst], 1);
    g_esrc[pos] = src;
    g_ebasis[pos] = *reinterpret_cast<uint4*>(hb);
}

// ---------------- edge agg, layer1: A[n][k*32+i] = (1/deg) * sum_e b_k * x[src][i] ----------------
__global__ void __launch_bounds__(256) edge_agg1_kernel(const float* __restrict__ x) {
    int wid = threadIdx.x >> 5, lane = threadIdx.x & 31;
    int n = blockIdx.x * 8 + wid;
    if (n >= NN) return;
    int start = __ldg(&g_off[n]), end = __ldg(&g_off[n + 1]);
    ull acc[4];
#pragma unroll
    for (int j = 0; j < 4; j++) acc[j] = 0ull;
    for (int e = start; e < end; e++) {
        int src = __ldg(&g_esrc[e]);
        uint4 bw = __ldg(&g_ebasis[e]);
        float xv = __ldg(&x[(size_t)src * 32 + lane]);
        const __half2* bh = reinterpret_cast<const __half2*>(&bw);
        ull ap = pk2(xv, xv);
#pragma unroll
        for (int j = 0; j < 4; j++) {
            float2 b = __half22float2(bh[j]);   // (b_{2j}, b_{2j+1})
            fma2(acc[j], ap, pk2(b.x, b.y));
        }
    }
    int deg = end - start;
    float inv = 1.0f / (float)(deg > 0 ? deg : 1);
    float* arow = g_A + (size_t)n * 256;
#pragma unroll
    for (int j = 0; j < 4; j++) {
        float2 v = upk2(acc[j]);
        arow[(2 * j) * 32 + lane]     = v.x * inv;
        arow[(2 * j + 1) * 32 + lane] = v.y * inv;
    }
}

// ---------------- edge agg, layer2: A[n][k*64+i] = (1/deg) * sum_e b_k * h[src][i] ----------------
__global__ void __launch_bounds__(256) edge_agg2_kernel() {
    int wid = threadIdx.x >> 5, lane = threadIdx.x & 31;
    int n = blockIdx.x * 8 + wid;
    if (n >= NN) return;
    int start = __ldg(&g_off[n]), end = __ldg(&g_off[n + 1]);
    ull acc[8];
#pragma unroll
    for (int k = 0; k < 8; k++) acc[k] = 0ull;
    for (int e = start; e < end; e++) {
        int src = __ldg(&g_esrc[e]);
        uint4 bw = __ldg(&g_ebasis[e]);
        float xv0 = __ldg(&g_h[(size_t)src * 64 + lane]);
        float xv1 = __ldg(&g_h[(size_t)src * 64 + 32 + lane]);
        const __half2* bh = reinterpret_cast<const __half2*>(&bw);
        ull ap = pk2(xv0, xv1);
#pragma unroll
        for (int j = 0; j < 4; j++) {
            float2 b = __half22float2(bh[j]);
            fma2(acc[2 * j],     ap, pk2(b.x, b.x));
            fma2(acc[2 * j + 1], ap, pk2(b.y, b.y));
        }
    }
    int deg = end - start;
    float inv = 1.0f / (float)(deg > 0 ? deg : 1);
    float* arow = g_A + (size_t)n * 512;
#pragma unroll
    for (int k = 0; k < 8; k++) {
        float2 v = upk2(acc[k]);
        arow[k * 64 + lane]      = v.x * inv;
        arow[k * 64 + 32 + lane] = v.y * inv;
    }
}

// ---------------- generic GEMM: out[n][o] = [A(n,:) | X(n,:)] @ [WA ; WB], fused BN stats ----------------
// K dim = nsteps*32; steps < split read A (weights WA), steps >= split read X (weights WB).
// Tile: 64 nodes x 64 cols per block, 128 threads, thread = 8 nodes x 4 cols, f32x2 FMA.
__global__ void __launch_bounds__(128) gemm_kernel(const float* __restrict__ A, int lda,
                                                   const float* __restrict__ X, int ldx,
                                                   const float* __restrict__ WA,
                                                   const float* __restrict__ WB,
                                                   int split, int nsteps,
                                                   float* __restrict__ out, int ostride,
                                                   int slot) {
    __shared__ float As[32][64];   // [k][node]
    __shared__ float Ws[32][64];   // [k][o]
    __shared__ float s_sum[64], s_sq[64];
    int tid = threadIdx.x;
    int n0 = blockIdx.x * 64;
    if (tid < 64) { s_sum[tid] = 0.f; s_sq[tid] = 0.f; }
    int ct = tid & 15;    // cols ct*4 .. ct*4+3
    int nt = tid >> 4;    // nodes nt*8 .. nt*8+7

    ull acc[4][4];        // [node-pair rp][col c]; node = nt*8 + 2*rp + {lo,hi}
#pragma unroll
    for (int a = 0; a < 4; a++)
#pragma unroll
        for (int b = 0; b < 4; b++) acc[a][b] = 0ull;

    for (int s = 0; s < nsteps; s++) {
        const float* src; int ld; int k0;
        if (s < split) { src = A; ld = lda; k0 = s * 32; }
        else           { src = X; ld = ldx; k0 = (s - split) * 32; }
        const float* wsrc = (s < split) ? (WA + (size_t)(s * 32) * 64)
                                        : (WB + (size_t)((s - split) * 32) * 64);
        __syncthreads();
#pragma unroll
        for (int i = 0; i < 4; i++) {
            int pos = tid + i * 128;            // 512 float4 slots for A tile
            int nl = pos >> 3, k4 = (pos & 7) * 4;
            int n = n0 + nl;
            float4 v = make_float4(0.f, 0.f, 0.f, 0.f);
            if (n < NN) v = *reinterpret_cast<const float4*>(&src[(size_t)n * ld + k0 + k4]);
            As[k4 + 0][nl] = v.x; As[k4 + 1][nl] = v.y;
            As[k4 + 2][nl] = v.z; As[k4 + 3][nl] = v.w;
        }
#pragma unroll
        for (int i = 0; i < 4; i++) {
            int pos = tid + i * 128;            // 512 float4 slots for W tile
            int k = pos >> 4, o4 = (pos & 15) * 4;
            *reinterpret_cast<float4*>(&Ws[k][o4]) =
                *reinterpret_cast<const float4*>(&wsrc[k * 64 + o4]);
        }
        __syncthreads();
#pragma unroll 4
        for (int k = 0; k < 32; k++) {
            float4 a0 = *reinterpret_cast<const float4*>(&As[k][nt * 8]);
            float4 a1 = *reinterpret_cast<const float4*>(&As[k][nt * 8 + 4]);
            float4 wv = *reinterpret_cast<const float4*>(&Ws[k][ct * 4]);
            ull ap[4] = { pk2(a0.x, a0.y), pk2(a0.z, a0.w),
                          pk2(a1.x, a1.y), pk2(a1.z, a1.w) };
            ull wp[4] = { pk2(wv.x, wv.x), pk2(wv.y, wv.y),
                          pk2(wv.z, wv.z), pk2(wv.w, wv.w) };
#pragma unroll
            for (int rp = 0; rp < 4; rp++)
#pragma unroll
                for (int c = 0; c < 4; c++) fma2(acc[rp][c], ap[rp], wp[c]);
        }
    }

    // epilogue: store + BN partial stats
    float csum[4] = {0.f, 0.f, 0.f, 0.f}, csq[4] = {0.f, 0.f, 0.f, 0.f};
#pragma unroll
    for (int rp = 0; rp < 4; rp++) {
        float2 f[4];
#pragma unroll
        for (int c = 0; c < 4; c++) f[c] = upk2(acc[rp][c]);
        int nA = n0 + nt * 8 + 2 * rp;
        if (nA < NN) {
            float4 vo = make_float4(f[0].x, f[1].x, f[2].x, f[3].x);
            *reinterpret_cast<float4*>(&out[(size_t)nA * ostride + ct * 4]) = vo;
            csum[0] += vo.x; csum[1] += vo.y; csum[2] += vo.z; csum[3] += vo.w;
            csq[0] += vo.x * vo.x; csq[1] += vo.y * vo.y;
            csq[2] += vo.z * vo.z; csq[3] += vo.w * vo.w;
        }
        int nB = nA + 1;
        if (nB < NN) {
            float4 vo = make_float4(f[0].y, f[1].y, f[2].y, f[3].y);
            *reinterpret_cast<float4*>(&out[(size_t)nB * ostride + ct * 4]) = vo;
            csum[0] += vo.x; csum[1] += vo.y; csum[2] += vo.z; csum[3] += vo.w;
            csq[0] += vo.x * vo.x; csq[1] += vo.y * vo.y;
            csq[2] += vo.z * vo.z; csq[3] += vo.w * vo.w;
        }
    }
#pragma unroll
    for (int c = 0; c < 4; c++) {
        atomicAdd(&s_sum[ct * 4 + c], csum[c]);
        atomicAdd(&s_sq[ct * 4 + c], csq[c]);
    }
    __syncthreads();
    if (tid < 64) {
        atomicAdd(&g_sum[slot * 64 + tid], s_sum[tid]);
        atomicAdd(&g_sq[slot * 64 + tid], s_sq[tid]);
    }
}

// ---------------- statfin: scale/shift for up to two slots ----------------
__global__ void statfin2_kernel(int slotA, const float* __restrict__ gA, const float* __restrict__ bA,
                                int slotB, const float* __restrict__ gB, const float* __restrict__ bB) {
    int t = threadIdx.x;
    if (t >= 128) return;
    int which = t >> 6;
    int o = t & 63;
    int slot = which ? slotB : slotA;
    if (slot < 0) return;
    const float* gamma = which ? gB : gA;
    const float* beta  = which ? bB : bA;
    float mu  = g_sum[slot * 64 + o] * (1.0f / NN);
    float var = g_sq[slot * 64 + o] * (1.0f / NN) - mu * mu;
    float sc  = gamma[o] * rsqrtf(var + 1e-5f);
    g_scale[slot * 64 + o] = sc;
    g_shift[slot * 64 + o] = beta[o] - mu * sc;
}

// ---------------- bn+elu on h (in place) ----------------
__global__ void __launch_bounds__(256) bnelu_kernel() {
    int i = blockIdx.x * 256 + threadIdx.x;
    if (i >= NN * 64) return;
    int o = i & 63;
    float v = g_h[i] * g_scale[o] + g_shift[o];
    g_h[i] = (v > 0.f) ? v : expm1f(v);
}

// ---------------- final: out = elu( BN(h2) + BN(skip) ) ----------------
__global__ void __launch_bounds__(256) final_kernel(float* __restrict__ out) {
    int i = blockIdx.x * 256 + threadIdx.x;
    if (i >= NN * 64) return;
    int o = i & 63;
    int n = i >> 6;
    float h2 = g_h[i] * g_scale[128 + o] + g_shift[128 + o];
    float s  = g_aux[(size_t)n * 128 + 64 + o] * g_scale[64 + o] + g_shift[64 + o];
    float v = h2 + s;
    out[i] = (v > 0.f) ? v : expm1f(v);
}

extern "C" void kernel_launch(void* const* d_in, const int* in_sizes, int n_in,
                              void* d_out, int out_size) {
    const float* x     = (const float*)d_in[0];
    const int*   ei    = (const int*)d_in[1];
    const float* ea    = (const float*)d_in[2];
    const float* W1    = (const float*)d_in[3];
    const float* root1 = (const float*)d_in[4];
    const float* g1    = (const float*)d_in[5];
    const float* b1    = (const float*)d_in[6];
    const float* W2    = (const float*)d_in[7];
    const float* root2 = (const float*)d_in[8];
    const float* g2    = (const float*)d_in[9];
    const float* b2    = (const float*)d_in[10];
    const float* Wsk   = (const float*)d_in[11];
    const float* gsk   = (const float*)d_in[12];
    const float* bsk   = (const float*)d_in[13];
    float* out = (float*)d_out;

    void *deg_p, *sum_p, *sq_p;
    cudaGetSymbolAddress(&deg_p, g_deg);
    cudaGetSymbolAddress(&sum_p, g_sum);
    cudaGetSymbolAddress(&sq_p, g_sq);

    cudaMemsetAsync(deg_p, 0, sizeof(int) * NN, 0);
    cudaMemsetAsync(sum_p, 0, sizeof(float) * 192, 0);
    cudaMemsetAsync(sq_p, 0, sizeof(float) * 192, 0);

    // ---- CSR build (shared by both layers) ----
    hist_kernel<<<(EE + 255) / 256, 256>>>(ei);
    scan_kernel<<<1, 1024>>>();
    scatter_kernel<<<(EE + 255) / 256, 256>>>(ei, ea);

    int gemm_grid = (NN + 63) / 64;
    float* aux_skip = ((float*)0) + 64;  // placeholder; real pointer computed below

    // ---- layer 1 ----
    edge_agg1_kernel<<<(NN + 7) / 8, 256>>>(x);
    // h1 = [A | x] @ [W1 ; root1]
    {
        void* hp; cudaGetSymbolAddress(&hp, g_h);
        void* ap; cudaGetSymbolAddress(&ap, g_A);
        void* auxp; cudaGetSymbolAddress(&auxp, g_aux);
        gemm_kernel<<<gemm_grid, 128>>>((const float*)ap, 256, x, 32,
                                        W1, root1, 8, 9, (float*)hp, 64, 0);
        // skip = x @ Wskip  (all steps from X/WB)
        gemm_kernel<<<gemm_grid, 128>>>((const float*)ap, 256, x, 32,
                                        Wsk, Wsk, 0, 1, (float*)auxp + 64, 128, 1);
        statfin2_kernel<<<1, 128>>>(0, g1, b1, 1, gsk, bsk);
        bnelu_kernel<<<(NN * 64 + 255) / 256, 256>>>();

        // ---- layer 2 ----
        edge_agg2_kernel<<<(NN + 7) / 8, 256>>>();
        gemm_kernel<<<gemm_grid, 128>>>((const float*)ap, 512, (const float*)hp, 64,
                                        W2, root2, 16, 18, (float*)hp, 64, 2);
        statfin2_kernel<<<1, 128>>>(2, g2, b2, -1, g2, b2);
        final_kernel<<<(NN * 64 + 255) / 256, 256>>>(out);
    }
    (void)aux_skip; (void)n_in; (void)in_sizes; (void)out_size;
}

// round 6
// speedup vs baseline: 2.6703x; 1.2260x over previous
#include <cuda_runtime.h>
#include <cuda_fp16.h>
#include <math.h>
#include <stdint.h>

#define NN 100000
#define EE 1600000

typedef unsigned long long ull;

// K dims (halfs): layer1 = 8*32 (A) + 32 (x) + 32 (pad) = 320 ; layer2 = 8*64 + 64 (h) = 576
#define K1 320
#define N1 128          // h (0..63) + skip (64..127)
#define K2 576
#define N2 64

// ---- scratch (device globals) ----
__device__ __half g_Ah[((size_t)NN + 256) * 640];  // fp16 A rows; stride 320 (L1) or 576 (L2)
__device__ __half g_Wt1[N1 * K1];                  // B operand layer1 [o][k]
__device__ __half g_Wt2[N2 * K2];                  // B operand layer2 [o][k]
__device__ float g_h[(size_t)NN * 64];             // h1 act, then h2 pre-BN
__device__ float g_skip[(size_t)NN * 64];          // skip pre-BN
__device__ int   g_deg[NN];
__device__ int   g_off[NN + 1];
__device__ int   g_cur[NN];
__device__ int   g_esrc[EE];
__device__ uint4 g_ebasis[EE];
__device__ float g_sum[192];
__device__ float g_sq[192];
__device__ float g_scale[192];
__device__ float g_shift[192];

// ---- f32x2 helpers ----
__device__ __forceinline__ ull pk2(float x, float y) {
    ull r; asm("mov.b64 %0, {%1, %2};" : "=l"(r) : "f"(x), "f"(y)); return r;
}
__device__ __forceinline__ void fma2(ull& d, ull a, ull b) {
    asm("fma.rn.f32x2 %0, %1, %2, %3;" : "=l"(d) : "l"(a), "l"(b), "l"(d));
}
__device__ __forceinline__ float2 upk2(ull v) {
    float2 f; asm("mov.b64 {%0, %1}, %2;" : "=f"(f.x), "=f"(f.y) : "l"(v)); return f;
}

// ---------------- CSR build ----------------
__global__ void __launch_bounds__(256) hist_kernel(const int* __restrict__ ei) {
    int e = blockIdx.x * 256 + threadIdx.x;
    if (e >= EE) return;
    atomicAdd(&g_deg[__ldg(&ei[EE + e])], 1);
}

__global__ void __launch_bounds__(1024) scan_kernel() {
    __shared__ int wsum[32];
    __shared__ int chunk_total;
    int tid = threadIdx.x, lane = tid & 31, wid = tid >> 5;
    int base = 0;
    for (int start = 0; start < NN; start += 1024) {
        int i = start + tid;
        int v = (i < NN) ? g_deg[i] : 0;
        int inc = v;
#pragma unroll
        for (int d = 1; d < 32; d <<= 1) {
            int t = __shfl_up_sync(0xffffffffu, inc, d);
            if (lane >= d) inc += t;
        }
        if (lane == 31) wsum[wid] = inc;
        __syncthreads();
        if (wid == 0) {
            int w = wsum[lane];
            int winc = w;
#pragma unroll
            for (int d = 1; d < 32; d <<= 1) {
                int t = __shfl_up_sync(0xffffffffu, winc, d);
                if (lane >= d) winc += t;
            }
            wsum[lane] = winc - w;
            if (lane == 31) chunk_total = winc;
        }
        __syncthreads();
        int excl = base + wsum[wid] + inc - v;
        if (i < NN) { g_off[i] = excl; g_cur[i] = excl; }
        base += chunk_total;
        __syncthreads();
    }
    if (tid == 0) g_off[NN] = base;
}

__global__ void __launch_bounds__(256) scatter_kernel(const int* __restrict__ ei,
                                                      const float* __restrict__ ea) {
    int e = blockIdx.x * 256 + threadIdx.x;
    if (e >= EE) return;
    int src = __ldg(&ei[e]);
    int dst = __ldg(&ei[EE + e]);
    float u0 = __ldg(&ea[e * 3 + 0]);
    float u1 = __ldg(&ea[e * 3 + 1]);
    float u2 = __ldg(&ea[e * 3 + 2]);
    float v0 = 1.f - u0, v1 = 1.f - u1, v2 = 1.f - u2;
    __align__(16) __half hb[8];
    hb[0] = __float2half(v0 * v1 * v2); hb[1] = __float2half(u0 * v1 * v2);
    hb[2] = __float2half(v0 * u1 * v2); hb[3] = __float2half(u0 * u1 * v2);
    hb[4] = __float2half(v0 * v1 * u2); hb[5] = __float2half(u0 * v1 * u2);
    hb[6] = __float2half(v0 * u1 * u2); hb[7] = __float2half(u0 * u1 * u2);
    int pos = atomicAdd(&g_cur[dst], 1);
    g_esrc[pos] = src;
    g_ebasis[pos] = *reinterpret_cast<uint4*>(hb);
}

// ---------------- wprep: fp16 B operands [o][k] ----------------
__global__ void __launch_bounds__(256) wprep_kernel(const float* __restrict__ W1,
                                                    const float* __restrict__ root1,
                                                    const float* __restrict__ Wsk,
                                                    const float* __restrict__ W2,
                                                    const float* __restrict__ root2) {
    int idx = blockIdx.x * 256 + threadIdx.x;
    if (idx < N1 * K1) {
        int o = idx / K1, k = idx % K1;
        float v = 0.f;
        if (o < 64) {
            if (k < 256)      v = W1[(k >> 5) * 2048 + (k & 31) * 64 + o];
            else if (k < 288) v = root1[(k - 256) * 64 + o];
        } else {
            if (k >= 256 && k < 288) v = Wsk[(k - 256) * 64 + (o - 64)];
        }
        g_Wt1[idx] = __float2half(v);
    } else {
        int i2 = idx - N1 * K1;
        if (i2 >= N2 * K2) return;
        int o = i2 / K2, k = i2 % K2;
        float v = (k < 512) ? W2[(k >> 6) * 4096 + (k & 63) * 64 + o]
                            : root2[(k - 512) * 64 + o];
        g_Wt2[i2] = __float2half(v);
    }
}

// ---------------- edge agg layer1 -> fp16 A rows (stride K1) ----------------
__global__ void __launch_bounds__(256) edge_agg1_kernel(const float* __restrict__ x) {
    int wid = threadIdx.x >> 5, lane = threadIdx.x & 31;
    int n = blockIdx.x * 8 + wid;
    if (n >= NN) return;
    int start = __ldg(&g_off[n]), end = __ldg(&g_off[n + 1]);
    ull acc[4];
#pragma unroll
    for (int j = 0; j < 4; j++) acc[j] = 0ull;
    for (int e = start; e < end; e++) {
        int src = __ldg(&g_esrc[e]);
        uint4 bw = __ldg(&g_ebasis[e]);
        float xv = __ldg(&x[(size_t)src * 32 + lane]);
        const __half2* bh = reinterpret_cast<const __half2*>(&bw);
        ull ap = pk2(xv, xv);
#pragma unroll
        for (int j = 0; j < 4; j++) {
            float2 b = __half22float2(bh[j]);
            fma2(acc[j], ap, pk2(b.x, b.y));
        }
    }
    int deg = end - start;
    float inv = 1.0f / (float)(deg > 0 ? deg : 1);
    __half* row = g_Ah + (size_t)n * K1;
#pragma unroll
    for (int j = 0; j < 4; j++) {
        float2 v = upk2(acc[j]);
        row[(2 * j) * 32 + lane]     = __float2half(v.x * inv);
        row[(2 * j + 1) * 32 + lane] = __float2half(v.y * inv);
    }
    row[256 + lane] = __float2half(__ldg(&x[(size_t)n * 32 + lane]));
    row[288 + lane] = __float2half(0.f);
}

// ---------------- edge agg layer2 -> fp16 A rows (stride K2) ----------------
__global__ void __launch_bounds__(256) edge_agg2_kernel() {
    int wid = threadIdx.x >> 5, lane = threadIdx.x & 31;
    int n = blockIdx.x * 8 + wid;
    if (n >= NN) return;
    int start = __ldg(&g_off[n]), end = __ldg(&g_off[n + 1]);
    ull acc[8];
#pragma unroll
    for (int k = 0; k < 8; k++) acc[k] = 0ull;
    const float2* hb2 = reinterpret_cast<const float2*>(g_h);
    for (int e = start; e < end; e++) {
        int src = __ldg(&g_esrc[e]);
        uint4 bw = __ldg(&g_ebasis[e]);
        float2 hv = __ldg(&hb2[(size_t)src * 32 + lane]);   // feats 2*lane, 2*lane+1
        const __half2* bh = reinterpret_cast<const __half2*>(&bw);
        ull ap = pk2(hv.x, hv.y);
#pragma unroll
        for (int j = 0; j < 4; j++) {
            float2 b = __half22float2(bh[j]);
            fma2(acc[2 * j],     ap, pk2(b.x, b.x));
            fma2(acc[2 * j + 1], ap, pk2(b.y, b.y));
        }
    }
    int deg = end - start;
    float inv = 1.0f / (float)(deg > 0 ? deg : 1);
    __half2* row = reinterpret_cast<__half2*>(g_Ah + (size_t)n * K2);
#pragma unroll
    for (int k = 0; k < 8; k++) {
        float2 v = upk2(acc[k]);
        row[k * 32 + lane] = __floats2half2_rn(v.x * inv, v.y * inv);
    }
}

// ---------------- HMMA GEMM: out[rows_pb][Ncols] per block = A @ Wt^T, fused BN stats ----------------
// A fp16 [n][K] global (frags loaded direct), B fp16 [o][K] staged to padded SMEM.
// Warp tile 32 rows x 64 cols (2 row-tiles x 8 n-tiles of m16n8k16).
// Layer1: rows_pb=128, Ncols=128 (8 warps = 4 row-grps x 2 col-grps), sumbase=0 (slots 0,1)
// Layer2: rows_pb=256, Ncols=64  (8 warps = 8 row-grps), sumbase=128 (slot 2)
__global__ void __launch_bounds__(256) gemm_mma_kernel(const __half* __restrict__ Aglob, int K,
                                                       const __half* __restrict__ Wt, int Ncols,
                                                       int rows_pb,
                                                       float* __restrict__ out0,
                                                       float* __restrict__ out1,
                                                       int sumbase) {
    extern __shared__ __half Bs[];
    __shared__ float s_sum[128], s_sq[128];
    int tid = threadIdx.x, warp = tid >> 5, lane = tid & 31;
    int gid = lane >> 2, t4 = lane & 3;
    int Kpad = K + 8;

    // stage B into padded SMEM
    for (int i = tid; i < Ncols * (K / 8); i += 256) {
        int o = i / (K / 8), p = i % (K / 8);
        *reinterpret_cast<uint4*>(&Bs[o * Kpad + p * 8]) =
            *reinterpret_cast<const uint4*>(&Wt[(size_t)o * K + p * 8]);
    }
    if (tid < 128) { s_sum[tid] = 0.f; s_sq[tid] = 0.f; }
    __syncthreads();

    int rwarps = rows_pb >> 5;                 // 4 or 8
    int roww = (warp & (rwarps - 1)) * 32;
    int colw = (warp / rwarps) * 64;
    int nbase = blockIdx.x * rows_pb + roww;

    float c[2][8][4];
#pragma unroll
    for (int rt = 0; rt < 2; rt++)
#pragma unroll
        for (int nt = 0; nt < 8; nt++)
#pragma unroll
            for (int q = 0; q < 4; q++) c[rt][nt][q] = 0.f;

    int ksteps = K >> 4;
    for (int ks = 0; ks < ksteps; ks++) {
        int k0 = ks * 16;
        uint32_t a[2][4];
#pragma unroll
        for (int rt = 0; rt < 2; rt++) {
            const __half* ar = Aglob + (size_t)(nbase + rt * 16 + gid) * K + k0 + t4 * 2;
            a[rt][0] = *reinterpret_cast<const uint32_t*>(ar);
            a[rt][2] = *reinterpret_cast<const uint32_t*>(ar + 8);
            const __half* ar8 = ar + (size_t)8 * K;
            a[rt][1] = *reinterpret_cast<const uint32_t*>(ar8);
            a[rt][3] = *reinterpret_cast<const uint32_t*>(ar8 + 8);
        }
#pragma unroll
        for (int nt = 0; nt < 8; nt++) {
            const __half* bp = Bs + (colw + nt * 8 + gid) * Kpad + k0 + t4 * 2;
            uint32_t b0 = *reinterpret_cast<const uint32_t*>(bp);
            uint32_t b1 = *reinterpret_cast<const uint32_t*>(bp + 8);
#pragma unroll
            for (int rt = 0; rt < 2; rt++) {
                asm volatile(
                    "mma.sync.aligned.m16n8k16.row.col.f32.f16.f16.f32 "
                    "{%0,%1,%2,%3}, {%4,%5,%6,%7}, {%8,%9}, {%0,%1,%2,%3};"
                    : "+f"(c[rt][nt][0]), "+f"(c[rt][nt][1]),
                      "+f"(c[rt][nt][2]), "+f"(c[rt][nt][3])
                    : "r"(a[rt][0]), "r"(a[rt][1]), "r"(a[rt][2]), "r"(a[rt][3]),
                      "r"(b0), "r"(b1));
            }
        }
    }

    // epilogue: store + per-thread column stats
    float ls[16], lq[16];
#pragma unroll
    for (int j = 0; j < 16; j++) { ls[j] = 0.f; lq[j] = 0.f; }
#pragma unroll
    for (int rt = 0; rt < 2; rt++) {
        int r0 = nbase + rt * 16 + gid;
        int r1 = r0 + 8;
#pragma unroll
        for (int nt = 0; nt < 8; nt++) {
            int col = colw + nt * 8 + t4 * 2;
            float v0 = c[rt][nt][0], v1 = c[rt][nt][1];
            float v2 = c[rt][nt][2], v3 = c[rt][nt][3];
            if (r0 < NN) {
                float* dst = (col < 64) ? (out0 + (size_t)r0 * 64 + col)
                                        : (out1 + (size_t)r0 * 64 + col - 64);
                *reinterpret_cast<float2*>(dst) = make_float2(v0, v1);
                ls[nt * 2] += v0; lq[nt * 2] += v0 * v0;
                ls[nt * 2 + 1] += v1; lq[nt * 2 + 1] += v1 * v1;
            }
            if (r1 < NN) {
                float* dst = (col < 64) ? (out0 + (size_t)r1 * 64 + col)
                                        : (out1 + (size_t)r1 * 64 + col - 64);
                *reinterpret_cast<float2*>(dst) = make_float2(v2, v3);
                ls[nt * 2] += v2; lq[nt * 2] += v2 * v2;
                ls[nt * 2 + 1] += v3; lq[nt * 2 + 1] += v3 * v3;
            }
        }
    }
#pragma unroll
    for (int nt = 0; nt < 8; nt++) {
#pragma unroll
        for (int j = 0; j < 2; j++) {
            int col = colw + nt * 8 + t4 * 2 + j;
            atomicAdd(&s_sum[col], ls[nt * 2 + j]);
            atomicAdd(&s_sq[col], lq[nt * 2 + j]);
        }
    }
    __syncthreads();
    if (tid < Ncols) {
        atomicAdd(&g_sum[sumbase + tid], s_sum[tid]);
        atomicAdd(&g_sq[sumbase + tid], s_sq[tid]);
    }
}

// ---------------- statfin: scale/shift for up to two slots ----------------
__global__ void statfin2_kernel(int slotA, const float* __restrict__ gA, const float* __restrict__ bA,
                                int slotB, const float* __restrict__ gB, const float* __restrict__ bB) {
    int t = threadIdx.x;
    if (t >= 128) return;
    int which = t >> 6;
    int o = t & 63;
    int slot = which ? slotB : slotA;
    if (slot < 0) return;
    const float* gamma = which ? gB : gA;
    const float* beta  = which ? bB : bA;
    float mu  = g_sum[slot * 64 + o] * (1.0f / NN);
    float var = g_sq[slot * 64 + o] * (1.0f / NN) - mu * mu;
    float sc  = gamma[o] * rsqrtf(var + 1e-5f);
    g_scale[slot * 64 + o] = sc;
    g_shift[slot * 64 + o] = beta[o] - mu * sc;
}

// ---------------- bn+elu on h; also writes fp16 concat slots of A2 ----------------
__global__ void __launch_bounds__(256) bnelu_kernel() {
    int i = blockIdx.x * 256 + threadIdx.x;
    if (i >= NN * 64) return;
    int o = i & 63;
    int n = i >> 6;
    float v = g_h[i] * g_scale[o] + g_shift[o];
    float e = (v > 0.f) ? v : expm1f(v);
    g_h[i] = e;
    g_Ah[(size_t)n * K2 + 512 + o] = __float2half(e);
}

// ---------------- final: out = elu( BN(h2) + BN(skip) ) ----------------
__global__ void __launch_bounds__(256) final_kernel(float* __restrict__ out) {
    int i = blockIdx.x * 256 + threadIdx.x;
    if (i >= NN * 64) return;
    int o = i & 63;
    float h2 = g_h[i] * g_scale[128 + o] + g_shift[128 + o];
    float s  = g_skip[i] * g_scale[64 + o] + g_shift[64 + o];
    float v = h2 + s;
    out[i] = (v > 0.f) ? v : expm1f(v);
}

extern "C" void kernel_launch(void* const* d_in, const int* in_sizes, int n_in,
                              void* d_out, int out_size) {
    const float* x     = (const float*)d_in[0];
    const int*   ei    = (const int*)d_in[1];
    const float* ea    = (const float*)d_in[2];
    const float* W1    = (const float*)d_in[3];
    const float* root1 = (const float*)d_in[4];
    const float* g1    = (const float*)d_in[5];
    const float* b1    = (const float*)d_in[6];
    const float* W2    = (const float*)d_in[7];
    const float* root2 = (const float*)d_in[8];
    const float* g2    = (const float*)d_in[9];
    const float* b2    = (const float*)d_in[10];
    const float* Wsk   = (const float*)d_in[11];
    const float* gsk   = (const float*)d_in[12];
    const float* bsk   = (const float*)d_in[13];
    float* out = (float*)d_out;

    void *deg_p, *sum_p, *sq_p, *ah_p, *wt1_p, *wt2_p, *h_p, *skip_p;
    cudaGetSymbolAddress(&deg_p, g_deg);
    cudaGetSymbolAddress(&sum_p, g_sum);
    cudaGetSymbolAddress(&sq_p, g_sq);
    cudaGetSymbolAddress(&ah_p, g_Ah);
    cudaGetSymbolAddress(&wt1_p, g_Wt1);
    cudaGetSymbolAddress(&wt2_p, g_Wt2);
    cudaGetSymbolAddress(&h_p, g_h);
    cudaGetSymbolAddress(&skip_p, g_skip);

    int smem1 = N1 * (K1 + 8) * 2;   // 83,968 B
    int smem2 = N2 * (K2 + 8) * 2;   // 74,752 B
    cudaFuncSetAttribute(gemm_mma_kernel, cudaFuncAttributeMaxDynamicSharedMemorySize, smem1);

    cudaMemsetAsync(deg_p, 0, sizeof(int) * NN, 0);
    cudaMemsetAsync(sum_p, 0, sizeof(float) * 192, 0);
    cudaMemsetAsync(sq_p, 0, sizeof(float) * 192, 0);

    // CSR build + weight prep
    hist_kernel<<<(EE + 255) / 256, 256>>>(ei);
    scan_kernel<<<1, 1024>>>();
    scatter_kernel<<<(EE + 255) / 256, 256>>>(ei, ea);
    wprep_kernel<<<(N1 * K1 + N2 * K2 + 255) / 256, 256>>>(W1, root1, Wsk, W2, root2);

    // ---- layer 1 ----
    edge_agg1_kernel<<<(NN + 7) / 8, 256>>>(x);
    gemm_mma_kernel<<<(NN + 127) / 128, 256, smem1>>>((const __half*)ah_p, K1,
                                                      (const __half*)wt1_p, N1, 128,
                                                      (float*)h_p, (float*)skip_p, 0);
    statfin2_kernel<<<1, 128>>>(0, g1, b1, 1, gsk, bsk);
    bnelu_kernel<<<(NN * 64 + 255) / 256, 256>>>();

    // ---- layer 2 ----
    edge_agg2_kernel<<<(NN + 7) / 8, 256>>>();
    gemm_mma_kernel<<<(NN + 255) / 256, 256, smem2>>>((const __half*)ah_p, K2,
                                                      (const __half*)wt2_p, N2, 256,
                                                      (float*)h_p, (float*)h_p, 128);
    statfin2_kernel<<<1, 128>>>(2, g2, b2, -1, g2, b2);
    final_kernel<<<(NN * 64 + 255) / 256, 256>>>(out);
    (void)n_in; (void)in_sizes; (void)out_size;
}